// round 1
// baseline (speedup 1.0000x reference)
#include <cuda_runtime.h>

// ---------------------------------------------------------------------------
// MaskRemoval: Mask R-CNN style mask pasting + per-class greedy suppression.
//
// Pipeline (all graph-capturable, allocation-free):
//   k_sort    : stable descending sort by cls_prob, box int-cast, cls-1
//   k_scan    : one CTA per class; sequential suppression scan over that
//               class's ROIs using a word-granular 800x800 bitmask in global
//               scratch (zeroed per launch by the owning CTA)
//   k_compact : cumsum of keep flags -> slot table + keep_inds output
//   k_fill    : streaming writer of the 100x800x800 f32 energy tensor
//               (256 MB, HBM-store bound); bilinear values only inside the
//               kept boxes, float4 zeros elsewhere.
// ---------------------------------------------------------------------------

#define MAXN   128
#define NCLS   80
#define MM     28
#define IMG_H  800
#define IMG_W  800
#define WPR    ((IMG_W + 31) / 32)   // 25 words per image row

__device__ int g_order[MAXN];                     // sorted idx -> original roi
__device__ int g_bx0[MAXN], g_by0[MAXN];
__device__ int g_bx1[MAXN], g_by1[MAXN];
__device__ int g_cls[MAXN];
__device__ int g_keep[MAXN];
__device__ int g_slot[MAXN];                      // output slot -> sorted idx (-1 = empty)
__device__ unsigned int g_cmask[NCLS][IMG_H * WPR];  // 6.4 MB class bitmasks

// ---------------------------------------------------------------------------
__global__ __launch_bounds__(128) void k_sort(const float* __restrict__ rois,
                                              const float* __restrict__ prob,
                                              const int*   __restrict__ clsidx,
                                              int N) {
    int i = threadIdx.x;
    if (i < N) {
        float pi = prob[i];
        int r = 0;
        for (int j = 0; j < N; j++) {
            float pj = prob[j];
            r += (pj > pi) || (pj == pi && j < i);   // stable descending rank
        }
        g_order[r] = i;
        g_keep[i] = 0;
    }
    __syncthreads();
    if (i < N) {
        int o = g_order[i];
        // jnp .astype(int32) truncates toward zero, matching (int) cast
        g_bx0[i] = (int)rois[4 * o + 0];
        g_by0[i] = (int)rois[4 * o + 1];
        g_bx1[i] = (int)rois[4 * o + 2];
        g_by1[i] = (int)rois[4 * o + 3];
        g_cls[i] = clsidx[o] - 1;
    }
}

// ---------------------------------------------------------------------------
__device__ __forceinline__ float bilin(const float* lg, float sx, float sy) {
    int ix0 = (int)sx;                 // sx,sy already clamped to [0,27]
    int iy0 = (int)sy;
    int ix1 = min(ix0 + 1, MM - 1);
    int iy1 = min(iy0 + 1, MM - 1);
    float fx = sx - (float)ix0;
    float fy = sy - (float)iy0;
    float v00 = lg[iy0 * MM + ix0], v01 = lg[iy0 * MM + ix1];
    float v10 = lg[iy1 * MM + ix0], v11 = lg[iy1 * MM + ix1];
    return (1.0f - fy) * ((1.0f - fx) * v00 + fx * v01)
         +         fy  * ((1.0f - fx) * v10 + fx * v11);
}

__global__ __launch_bounds__(256) void k_scan(const float* __restrict__ mask_prob,
                                              int N) {
    int c = blockIdx.x;
    unsigned int* cm = g_cmask[c];
    __shared__ float lg[MM * MM];
    __shared__ int s_msum, s_ovl, s_keep;

    // zero this class's bitmask
    for (int w = threadIdx.x; w < IMG_H * WPR; w += blockDim.x) cm[w] = 0u;
    __syncthreads();

    for (int i = 0; i < N; i++) {
        if (g_cls[i] != c) continue;                      // uniform branch

        int x0 = g_bx0[i], y0 = g_by0[i], x1 = g_bx1[i], y1 = g_by1[i];
        int xs0 = max(x0, 0), xs1 = min(x1 + 1, IMG_W);
        int ys0 = max(y0, 0), ys1 = min(y1 + 1, IMG_H);

        int o = g_order[i];
        const float* lp = mask_prob + (long long)o * (MM * MM);
        for (int t = threadIdx.x; t < MM * MM; t += blockDim.x) lg[t] = lp[t];
        if (threadIdx.x == 0) { s_msum = 0; s_ovl = 0; }
        __syncthreads();

        float wv = fmaxf((float)(x1 - x0 + 1), 1.0f);
        float hv = fmaxf((float)(y1 - y0 + 1), 1.0f);
        float scx = 28.0f / wv, scy = 28.0f / hv;
        float x0f = (float)x0, y0f = (float)y0;

        int lm = 0, lo = 0;
        bool nonempty = (xs0 < xs1) && (ys0 < ys1);
        int xw0 = xs0 >> 5, xw1 = (xs1 + 31) >> 5;
        int nwx = xw1 - xw0;
        int total = nonempty ? nwx * (ys1 - ys0) : 0;

        // pass 1: count msum and overlap with accumulated class mask
        for (int k = threadIdx.x; k < total; k += blockDim.x) {
            int ry = k / nwx;
            int y  = ys0 + ry;
            int xw = xw0 + (k - ry * nwx);
            unsigned int cw = cm[y * WPR + xw];
            float sy = fminf(fmaxf(((float)y - y0f + 0.5f) * scy - 0.5f, 0.0f), 27.0f);
            int xlo = max(xs0, xw << 5);
            int xhi = min(xs1, (xw << 5) + 32);
            for (int x = xlo; x < xhi; x++) {
                float sx = fminf(fmaxf(((float)x - x0f + 0.5f) * scx - 0.5f, 0.0f), 27.0f);
                float val = bilin(lg, sx, sy);
                if (val > 0.0f) {
                    lm++;
                    if (cw & (1u << (x & 31))) lo++;
                }
            }
        }
        #pragma unroll
        for (int off = 16; off > 0; off >>= 1) {
            lm += __shfl_down_sync(0xffffffffu, lm, off);
            lo += __shfl_down_sync(0xffffffffu, lo, off);
        }
        if ((threadIdx.x & 31) == 0) { atomicAdd(&s_msum, lm); atomicAdd(&s_ovl, lo); }
        __syncthreads();

        if (threadIdx.x == 0) {
            float ms = (float)s_msum, ov = (float)s_ovl;
            int kp = (ms > 0.0f) && (ov <= 0.3f * ms);
            s_keep = kp;
            g_keep[i] = kp;
        }
        __syncthreads();

        // pass 2: merge kept mask into class bitmask (word-granular, no atomics)
        if (s_keep) {
            for (int k = threadIdx.x; k < total; k += blockDim.x) {
                int ry = k / nwx;
                int y  = ys0 + ry;
                int xw = xw0 + (k - ry * nwx);
                float sy = fminf(fmaxf(((float)y - y0f + 0.5f) * scy - 0.5f, 0.0f), 27.0f);
                int xlo = max(xs0, xw << 5);
                int xhi = min(xs1, (xw << 5) + 32);
                unsigned int bits = 0u;
                for (int x = xlo; x < xhi; x++) {
                    float sx = fminf(fmaxf(((float)x - x0f + 0.5f) * scx - 0.5f, 0.0f), 27.0f);
                    if (bilin(lg, sx, sy) > 0.0f) bits |= (1u << (x & 31));
                }
                if (bits) cm[y * WPR + xw] |= bits;
            }
        }
        __syncthreads();
    }
}

// ---------------------------------------------------------------------------
__global__ void k_compact(float* __restrict__ out_keep, int N, int has_keep) {
    if (threadIdx.x == 0) {
        for (int j = 0; j < N; j++) g_slot[j] = -1;
        int pos = 0;
        for (int i = 0; i < N; i++)
            if (g_keep[i]) g_slot[pos++] = i;
        if (has_keep) {
            for (int j = 0; j < N; j++) {
                int s = g_slot[j];
                out_keep[j] = (s >= 0) ? (float)g_order[s] : -1.0f;
            }
        }
    }
}

// ---------------------------------------------------------------------------
// One block per (row, slot). 256 MB of stores total — this is the kernel
// that must run at HBM store bandwidth.
__global__ __launch_bounds__(256) void k_fill(const float* __restrict__ mask_prob,
                                              float* __restrict__ energy) {
    int y    = blockIdx.x;
    int slot = blockIdx.y;
    float* row = energy + ((long long)slot * IMG_H + y) * IMG_W;
    int t = threadIdx.x;

    int s = g_slot[slot];
    bool inband = false;
    int x0 = 0, y0 = 0, x1 = 0, y1 = 0, xs0 = 0, xs1 = 0;
    if (s >= 0) {
        x0 = g_bx0[s]; y0 = g_by0[s]; x1 = g_bx1[s]; y1 = g_by1[s];
        int ys0 = max(y0, 0), ys1 = min(y1 + 1, IMG_H);
        xs0 = max(x0, 0); xs1 = min(x1 + 1, IMG_W);
        inband = (y >= ys0) && (y < ys1) && (xs0 < xs1);
    }

    if (!inband) {                       // pure zero row: vectorized stream
        if (t < IMG_W / 4)
            reinterpret_cast<float4*>(row)[t] = make_float4(0.f, 0.f, 0.f, 0.f);
        return;
    }

    __shared__ float lg[MM * MM];
    int o = g_order[s];
    const float* lp = mask_prob + (long long)o * (MM * MM);
    for (int k = t; k < MM * MM; k += blockDim.x) lg[k] = lp[k];
    __syncthreads();

    if (t < IMG_W / 4) {
        float wv = fmaxf((float)(x1 - x0 + 1), 1.0f);
        float hv = fmaxf((float)(y1 - y0 + 1), 1.0f);
        float scx = 28.0f / wv, scy = 28.0f / hv;
        float sy = fminf(fmaxf(((float)y - (float)y0 + 0.5f) * scy - 0.5f, 0.0f), 27.0f);
        float x0f = (float)x0;

        float4 v = make_float4(0.f, 0.f, 0.f, 0.f);
        int xb = t * 4;
        #pragma unroll
        for (int l = 0; l < 4; l++) {
            int x = xb + l;
            if (x >= xs0 && x < xs1) {
                float sx = fminf(fmaxf(((float)x - x0f + 0.5f) * scx - 0.5f, 0.0f), 27.0f);
                reinterpret_cast<float*>(&v)[l] = bilin(lg, sx, sy);
            }
        }
        reinterpret_cast<float4*>(row)[t] = v;
    }
}

// ---------------------------------------------------------------------------
extern "C" void kernel_launch(void* const* d_in, const int* in_sizes, int n_in,
                              void* d_out, int out_size) {
    const float* rois  = (const float*)d_in[0];   // (N,4) f32
    const float* prob  = (const float*)d_in[1];   // (N,)  f32
    const float* mp    = (const float*)d_in[2];   // (N,28,28) f32
    const int*   cidx  = (const int*)d_in[3];     // (N,)  i32

    int N = in_sizes[1];                          // cls_prob element count
    if (N > MAXN) N = MAXN;

    float* out = (float*)d_out;
    long long HW = (long long)IMG_H * IMG_W;
    // Expected layout: keep_inds (N floats) followed by mask_energy (N*H*W).
    int has_keep = ((long long)out_size == (long long)N + (long long)N * HW) ? 1 : 0;
    float* energy = out + (has_keep ? N : 0);

    k_sort<<<1, 128>>>(rois, prob, cidx, N);
    k_scan<<<NCLS, 256>>>(mp, N);
    k_compact<<<1, 32>>>(out, N, has_keep);
    k_fill<<<dim3(IMG_H, N), 256>>>(mp, energy);
}

// round 2
// speedup vs baseline: 1.1948x; 1.1948x over previous
#include <cuda_runtime.h>

// ---------------------------------------------------------------------------
// MaskRemoval — R2: split streaming-zero from paste, single-pass bitmask scan,
// parallel compaction.
//
//   k_sort    : stable descending rank sort (1 CTA)
//   k_scan    : one CTA/class; per-ROI single bilinear pass -> bits in shared,
//               popc counting, memory-only merge into class bitmask
//   k_compact : 128-thread prefix scan -> slot table + keep_inds
//   k_zero    : grid-stride float4 zero of the 256MB energy tensor (HBM-bound)
//   k_paste   : one CTA per kept slot, writes bilinear values inside its box
// ---------------------------------------------------------------------------

#define MAXN   128
#define NCLS   80
#define MM     28
#define IMG_H  800
#define IMG_W  800
#define WPR    ((IMG_W + 31) / 32)     // 25 words per image row
#define BOXMAX 352                     // max clipped box extent we precompute
#define BITS_WORDS 6144                // 11 words/row * 302 rows fits easily

__device__ int g_order[MAXN];
__device__ int g_bx0[MAXN], g_by0[MAXN];
__device__ int g_bx1[MAXN], g_by1[MAXN];
__device__ int g_cls[MAXN];
__device__ int g_keep[MAXN];
__device__ int g_slot[MAXN];
__device__ unsigned int g_cmask[NCLS][IMG_H * WPR];   // 6.4 MB

// ---------------------------------------------------------------------------
__global__ __launch_bounds__(128) void k_sort(const float* __restrict__ rois,
                                              const float* __restrict__ prob,
                                              const int*   __restrict__ clsidx,
                                              int N) {
    int i = threadIdx.x;
    if (i < N) {
        float pi = prob[i];
        int r = 0;
        for (int j = 0; j < N; j++) {
            float pj = prob[j];
            r += (pj > pi) || (pj == pi && j < i);    // stable descending rank
        }
        g_order[r] = i;
        g_keep[i] = 0;
    }
    __syncthreads();
    if (i < N) {
        int o = g_order[i];
        g_bx0[i] = (int)rois[4 * o + 0];   // trunc-toward-zero matches astype(int32)
        g_by0[i] = (int)rois[4 * o + 1];
        g_bx1[i] = (int)rois[4 * o + 2];
        g_by1[i] = (int)rois[4 * o + 3];
        g_cls[i] = clsidx[o] - 1;
    }
}

// exact reference bilinear form (keep decision thresholds on val>0)
__device__ __forceinline__ float bilin_ref(const float* lg, float sx, float sy) {
    int ix0 = (int)sx;
    int iy0 = (int)sy;
    int ix1 = min(ix0 + 1, MM - 1);
    int iy1 = min(iy0 + 1, MM - 1);
    float fx = sx - (float)ix0;
    float fy = sy - (float)iy0;
    float v00 = lg[iy0 * MM + ix0], v01 = lg[iy0 * MM + ix1];
    float v10 = lg[iy1 * MM + ix0], v11 = lg[iy1 * MM + ix1];
    return (1.0f - fy) * ((1.0f - fx) * v00 + fx * v01)
         +         fy  * ((1.0f - fx) * v10 + fx * v11);
}

// ---------------------------------------------------------------------------
__global__ __launch_bounds__(256) void k_scan(const float* __restrict__ mask_prob,
                                              int N) {
    int c = blockIdx.x;
    unsigned int* cm = g_cmask[c];

    __shared__ float lg[MM * MM];
    __shared__ float s_sx[BOXMAX];     // clamped sample x per box column
    __shared__ float s_sy[BOXMAX];     // clamped sample y per box row
    __shared__ unsigned int s_bits[BITS_WORDS];
    __shared__ int s_msum, s_ovl, s_keep;

    // zero this class's bitmask
    for (int w = threadIdx.x; w < IMG_H * WPR; w += blockDim.x) cm[w] = 0u;
    __syncthreads();

    for (int i = 0; i < N; i++) {
        if (g_cls[i] != c) continue;                  // uniform per-CTA branch

        int x0 = g_bx0[i], y0 = g_by0[i], x1 = g_bx1[i], y1 = g_by1[i];
        int xs0 = max(x0, 0), xs1 = min(x1 + 1, IMG_W);
        int ys0 = max(y0, 0), ys1 = min(y1 + 1, IMG_H);
        int bw = xs1 - xs0, bh = ys1 - ys0;

        int o = g_order[i];
        const float* lp = mask_prob + (long long)o * (MM * MM);
        for (int t = threadIdx.x; t < MM * MM; t += blockDim.x) lg[t] = lp[t];
        if (threadIdx.x == 0) { s_msum = 0; s_ovl = 0; }

        float wv = fmaxf((float)(x1 - x0 + 1), 1.0f);
        float hv = fmaxf((float)(y1 - y0 + 1), 1.0f);
        float scx = 28.0f / wv, scy = 28.0f / hv;

        if (bw > 0 && bw <= BOXMAX)
            for (int t = threadIdx.x; t < bw; t += blockDim.x)
                s_sx[t] = fminf(fmaxf(((float)(xs0 + t) - (float)x0 + 0.5f) * scx - 0.5f, 0.0f), 27.0f);
        if (bh > 0 && bh <= BOXMAX)
            for (int t = threadIdx.x; t < bh; t += blockDim.x)
                s_sy[t] = fminf(fmaxf(((float)(ys0 + t) - (float)y0 + 0.5f) * scy - 0.5f, 0.0f), 27.0f);
        __syncthreads();

        bool nonempty = (bw > 0) && (bh > 0);
        int xw0 = xs0 >> 5, xw1 = (xs1 + 31) >> 5;
        int nwx = xw1 - xw0;
        int total = nonempty ? nwx * bh : 0;
        bool fits = (total <= BITS_WORDS) && (bw <= BOXMAX) && (bh <= BOXMAX);

        int lm = 0, lo = 0;
        if (fits) {
            // single pass: build bits per 32-pixel word, popc-count
            for (int k = threadIdx.x; k < total; k += blockDim.x) {
                int ry = k / nwx;
                int y  = ys0 + ry;
                int xw = xw0 + (k - ry * nwx);
                float sy = s_sy[ry];
                int iy0 = (int)sy;
                int iy1 = min(iy0 + 1, MM - 1);
                float fy = sy - (float)iy0;
                const float* r0 = lg + iy0 * MM;
                const float* r1 = lg + iy1 * MM;
                int xlo = max(xs0, xw << 5);
                int xhi = min(xs1, (xw << 5) + 32);
                unsigned int bits = 0u;
                for (int x = xlo; x < xhi; x++) {
                    float sx = s_sx[x - xs0];
                    int ix0 = (int)sx;
                    int ix1 = min(ix0 + 1, MM - 1);
                    float fx = sx - (float)ix0;
                    float val = (1.0f - fy) * ((1.0f - fx) * r0[ix0] + fx * r0[ix1])
                              +         fy  * ((1.0f - fx) * r1[ix0] + fx * r1[ix1]);
                    if (val > 0.0f) bits |= (1u << (x & 31));
                }
                s_bits[k] = bits;
                lm += __popc(bits);
                lo += __popc(bits & cm[y * WPR + xw]);
            }
        } else if (nonempty) {
            // fallback (shouldn't trigger for these shapes)
            for (int k = threadIdx.x; k < total; k += blockDim.x) {
                int ry = k / nwx;
                int y  = ys0 + ry;
                int xw = xw0 + (k - ry * nwx);
                float sy = fminf(fmaxf(((float)y - (float)y0 + 0.5f) * scy - 0.5f, 0.0f), 27.0f);
                unsigned int cw = cm[y * WPR + xw];
                int xlo = max(xs0, xw << 5);
                int xhi = min(xs1, (xw << 5) + 32);
                for (int x = xlo; x < xhi; x++) {
                    float sx = fminf(fmaxf(((float)x - (float)x0 + 0.5f) * scx - 0.5f, 0.0f), 27.0f);
                    float val = bilin_ref(lg, sx, sy);
                    if (val > 0.0f) {
                        lm++;
                        if (cw & (1u << (x & 31))) lo++;
                    }
                }
            }
        }

        #pragma unroll
        for (int off = 16; off > 0; off >>= 1) {
            lm += __shfl_down_sync(0xffffffffu, lm, off);
            lo += __shfl_down_sync(0xffffffffu, lo, off);
        }
        if ((threadIdx.x & 31) == 0) { atomicAdd(&s_msum, lm); atomicAdd(&s_ovl, lo); }
        __syncthreads();

        if (threadIdx.x == 0) {
            float ms = (float)s_msum, ov = (float)s_ovl;
            int kp = (ms > 0.0f) && (ov <= 0.3f * ms);
            s_keep = kp;
            g_keep[i] = kp;
        }
        __syncthreads();

        if (s_keep) {
            if (fits) {
                // memory-only merge of cached bits
                for (int k = threadIdx.x; k < total; k += blockDim.x) {
                    unsigned int b = s_bits[k];
                    if (b) {
                        int ry = k / nwx;
                        int y  = ys0 + ry;
                        int xw = xw0 + (k - ry * nwx);
                        cm[y * WPR + xw] |= b;
                    }
                }
            } else if (nonempty) {
                for (int k = threadIdx.x; k < total; k += blockDim.x) {
                    int ry = k / nwx;
                    int y  = ys0 + ry;
                    int xw = xw0 + (k - ry * nwx);
                    float sy = fminf(fmaxf(((float)y - (float)y0 + 0.5f) * scy - 0.5f, 0.0f), 27.0f);
                    int xlo = max(xs0, xw << 5);
                    int xhi = min(xs1, (xw << 5) + 32);
                    unsigned int bits = 0u;
                    for (int x = xlo; x < xhi; x++) {
                        float sx = fminf(fmaxf(((float)x - (float)x0 + 0.5f) * scx - 0.5f, 0.0f), 27.0f);
                        if (bilin_ref(lg, sx, sy) > 0.0f) bits |= (1u << (x & 31));
                    }
                    if (bits) cm[y * WPR + xw] |= bits;
                }
            }
        }
        __syncthreads();
    }
}

// ---------------------------------------------------------------------------
__global__ __launch_bounds__(128) void k_compact(float* __restrict__ out_keep,
                                                 int N, int has_keep) {
    __shared__ int pf[128];
    int i = threadIdx.x;
    int k = (i < N) ? g_keep[i] : 0;
    pf[i] = k;
    __syncthreads();
    #pragma unroll
    for (int off = 1; off < 128; off <<= 1) {
        int v = (i >= off) ? pf[i - off] : 0;
        __syncthreads();
        pf[i] += v;
        __syncthreads();
    }
    if (i < N) g_slot[i] = -1;
    __syncthreads();
    if (i < N && k) g_slot[pf[i] - 1] = i;
    __syncthreads();
    if (has_keep && i < N) {
        int s = g_slot[i];
        out_keep[i] = (s >= 0) ? (float)g_order[s] : -1.0f;
    }
}

// ---------------------------------------------------------------------------
// Pure streaming zero of the energy tensor (the 256 MB HBM-bound part).
__global__ __launch_bounds__(256) void k_zero(float4* __restrict__ p, long long n4) {
    long long i = (long long)blockIdx.x * blockDim.x + threadIdx.x;
    long long stride = (long long)gridDim.x * blockDim.x;
    float4 z = make_float4(0.f, 0.f, 0.f, 0.f);
    for (; i < n4; i += stride) p[i] = z;
}

// ---------------------------------------------------------------------------
// One CTA per output slot: write bilinear values inside the kept box.
__global__ __launch_bounds__(256) void k_paste(const float* __restrict__ mask_prob,
                                               float* __restrict__ energy) {
    int slot = blockIdx.x;
    int s = g_slot[slot];
    if (s < 0) return;

    __shared__ float lg[MM * MM];
    int o = g_order[s];
    const float* lp = mask_prob + (long long)o * (MM * MM);
    for (int t = threadIdx.x; t < MM * MM; t += blockDim.x) lg[t] = lp[t];
    __syncthreads();

    int x0 = g_bx0[s], y0 = g_by0[s], x1 = g_bx1[s], y1 = g_by1[s];
    int xs0 = max(x0, 0), xs1 = min(x1 + 1, IMG_W);
    int ys0 = max(y0, 0), ys1 = min(y1 + 1, IMG_H);
    int bw = xs1 - xs0, bh = ys1 - ys0;
    if (bw <= 0 || bh <= 0) return;

    float wv = fmaxf((float)(x1 - x0 + 1), 1.0f);
    float hv = fmaxf((float)(y1 - y0 + 1), 1.0f);
    float scx = 28.0f / wv, scy = 28.0f / hv;

    float* base = energy + (long long)slot * IMG_H * IMG_W;
    int total = bw * bh;
    for (int k = threadIdx.x; k < total; k += blockDim.x) {
        int ry = k / bw;
        int rx = k - ry * bw;
        int y = ys0 + ry, x = xs0 + rx;
        float sy = fminf(fmaxf(((float)y - (float)y0 + 0.5f) * scy - 0.5f, 0.0f), 27.0f);
        float sx = fminf(fmaxf(((float)x - (float)x0 + 0.5f) * scx - 0.5f, 0.0f), 27.0f);
        base[y * IMG_W + x] = bilin_ref(lg, sx, sy);
    }
}

// ---------------------------------------------------------------------------
extern "C" void kernel_launch(void* const* d_in, const int* in_sizes, int n_in,
                              void* d_out, int out_size) {
    const float* rois  = (const float*)d_in[0];
    const float* prob  = (const float*)d_in[1];
    const float* mp    = (const float*)d_in[2];
    const int*   cidx  = (const int*)d_in[3];

    int N = in_sizes[1];
    if (N > MAXN) N = MAXN;

    float* out = (float*)d_out;
    long long HW = (long long)IMG_H * IMG_W;
    int has_keep = ((long long)out_size == (long long)N + (long long)N * HW) ? 1 : 0;
    float* energy = out + (has_keep ? N : 0);
    long long n4 = ((long long)N * HW) / 4;        // 800*800 % 4 == 0

    k_sort<<<1, 128>>>(rois, prob, cidx, N);
    k_scan<<<NCLS, 256>>>(mp, N);
    k_compact<<<1, 128>>>(out, N, has_keep);
    k_zero<<<2048, 256>>>((float4*)energy, n4);
    k_paste<<<N, 256>>>(mp, energy);
}